// round 15
// baseline (speedup 1.0000x reference)
#include <cuda_runtime.h>
#include <stdint.h>

#define REP      640
#define ROWS     16
#define NOCT     2              // 8-row groups per CTA
#define NSEG     8              // program octiles
#define NBIN     32             // 32-channel output bins (out_dim <= 1024)
#define MAXM     32768
#define MAXSTEP  1024
#define MAXPROG  (MAXSTEP + NBIN)
#define BLOCK    512

// -------- device-global scratch --------
__device__ __align__(16) uint4 g_prog[MAXPROG];  // {ab|bin<<20|flush<<31, 0, cg, cg}
__device__ int g_q[NSEG + 1];                    // octile slot boundaries
__device__ int g_irregular;
__device__ int g_is64;

__device__ __forceinline__ int geti(const void* p, int i, int is64) {
    return is64 ? (int)((const long long*)p)[i] : ((const int*)p)[i];
}

// ---- prep: heads at lane 0 (shfl continuity); bin; flush-tagged program ----
__global__ void k_prep(const void* __restrict__ r1, const void* __restrict__ r2,
                       const void* __restrict__ ro, const float* __restrict__ cg,
                       int M, int out_dim) {
    __shared__ unsigned sab[MAXSTEP], scgv[MAXSTEP];
    __shared__ unsigned short sbin[MAXSTEP], spos[MAXSTEP];
    __shared__ int scnt[NBIN], sdum[NBIN], sbase[NBIN + 1];
    __shared__ unsigned s_or;
    __shared__ int s_irr;
    int t = threadIdx.x;
    int lane = t & 31;
    const unsigned* cgu = (const unsigned*)cg;

    if (t < NBIN) { scnt[t] = 0; sdum[t] = 0; }
    if (t == 0) { s_or = 0u; s_irr = ((M & 31) || M > MAXM) ? 1 : 0; }
    __syncthreads();
    int Mc = (M > MAXM) ? MAXM : M;

    // int64 detect: odd 32-bit words of ro all zero -> int64
    {
        const unsigned* rr = (const unsigned*)ro;
        int lim = (Mc < 4096) ? Mc : 4096;
        unsigned v = 0;
        for (int i = 1 + 2 * t; i < lim; i += 2048) v |= rr[i];
        if (v) s_or = 1u;
    }
    __syncthreads();
    int is64 = (s_or == 0u);
    if (t == 0) g_is64 = is64;

    // verify + emit: i = base + t, so i%32 == lane; lane0 = step head
    for (int base = 0; base < Mc; base += 1024) {
        int i = base + t;
        int act = (i < Mc);
        int a = 0, b = 0, o = 0; unsigned cv = 0u;
        if (act) {
            a = geti(r1, i, is64); b = geti(r2, i, is64);
            o = geti(ro, i, is64); cv = cgu[i];
        }
        int pa = __shfl_up_sync(0xffffffffu, a, 1);
        int pb = __shfl_up_sync(0xffffffffu, b, 1);
        int po = __shfl_up_sync(0xffffffffu, o, 1);
        unsigned pc = __shfl_up_sync(0xffffffffu, cv, 1);
        if (act) {
            if (lane) {
                if (a != pa + 1 || b != pb + 1 || o != po + 1 || cv != pc)
                    s_irr = 1;
            } else {
                int s = i >> 5;
                int bin = o >> 5;
                if ((o & 31) || (unsigned)a > (unsigned)(REP - 32) ||
                    (unsigned)b > (unsigned)(REP - 32) || (unsigned)bin >= NBIN) {
                    s_irr = 1; a = 0; b = 0; bin = 0;
                }
                sab[s]  = (unsigned)a | ((unsigned)b << 10);
                scgv[s] = cv;
                sbin[s] = (unsigned short)bin;
                spos[s] = (unsigned short)atomicAdd(&scnt[bin], 1);
            }
        }
    }
    __syncthreads();

    // covered empty bins get one dummy slot (flush of acc=0 zero-fills block)
    int nblk = (out_dim + 31) >> 5;
    if (nblk > NBIN) nblk = NBIN;
    if (t < NBIN && t < nblk && scnt[t] == 0) { scnt[t] = 1; sdum[t] = 1; }
    __syncthreads();

    // warp-0 shuffle scan over 32 bins
    if (t < 32) {
        int v = scnt[t], inc = v;
        for (int off = 1; off < 32; off <<= 1) {
            int u = __shfl_up_sync(0xffffffffu, inc, off);
            if (t >= off) inc += u;
        }
        sbase[t] = inc - v;
        if (t == 31) sbase[32] = inc;
    }
    __syncthreads();

    int S = Mc >> 5;
    if (t == 0) {
        g_irregular = s_irr;
        int Sp = sbase[NBIN];
        g_q[0] = 0; g_q[NSEG] = Sp;
        for (int k = 1; k < NSEG; ++k) {
            int target = (Sp * k) / NSEG, best = 0, bd = 1 << 30;
            for (int b = 0; b <= NBIN; ++b) {
                int d = sbase[b] - target; if (d < 0) d = -d;
                if (d < bd) { bd = d; best = sbase[b]; }
            }
            g_q[k] = best;
        }
    }
    __syncthreads();

    // scatter into bin-ordered program; flush on last slot of each bin
    for (int s = t; s < S; s += 1024) {
        int bin = sbin[s];
        int slot = sbase[bin] + spos[s];
        unsigned fl = (slot == sbase[bin + 1] - 1) ? 0x80000000u : 0u;
        g_prog[slot] = make_uint4(sab[s] | ((unsigned)bin << 20) | fl,
                                  0u, scgv[s], scgv[s]);
    }
    if (t < NBIN && sdum[t])
        g_prog[sbase[t]] = make_uint4(((unsigned)t << 20) | 0x80000000u, 0u, 0u, 0u);
}

// ---- main: warp = 8-row oct, flat flush-bit loop, program in global ----
__global__ __launch_bounds__(BLOCK, 2)
void k_main(const float* __restrict__ x1, const float* __restrict__ x2,
            float* __restrict__ out, int N, int out_dim,
            const void* __restrict__ r1, const void* __restrict__ r2,
            const void* __restrict__ ro, const float* __restrict__ cg, int M) {
    extern __shared__ __align__(16) char smraw[];
    int tid  = threadIdx.x;
    int lane = tid & 31;
    int w    = tid >> 5;
    int rowbase = blockIdx.x * ROWS;

    if (!g_irregular) {
        // xs[arr][oct][channel] : 32 B (8 rows) per channel
        uint4* xs = (uint4*)smraw;                        // [2][NOCT][REP][2 uint4]

        if (rowbase + ROWS <= N) {
            for (int i = tid; i < NOCT * REP; i += BLOCK) {
                int q = i / REP, c = i - q * REP;
                const float* b1 = x1 + (size_t)(rowbase + 8 * q) * REP + c;
                const float* b2 = x2 + (size_t)(rowbase + 8 * q) * REP + c;
                float4 lo1 = make_float4(b1[0],       b1[REP],     b1[2 * REP], b1[3 * REP]);
                float4 hi1 = make_float4(b1[4 * REP], b1[5 * REP], b1[6 * REP], b1[7 * REP]);
                float4 lo2 = make_float4(b2[0],       b2[REP],     b2[2 * REP], b2[3 * REP]);
                float4 hi2 = make_float4(b2[4 * REP], b2[5 * REP], b2[6 * REP], b2[7 * REP]);
                ((float4*)xs)[i * 2]                        = lo1;
                ((float4*)xs)[i * 2 + 1]                    = hi1;
                ((float4*)xs)[(NOCT * REP + i) * 2]         = lo2;
                ((float4*)xs)[(NOCT * REP + i) * 2 + 1]     = hi2;
            }
        } else {
            for (int i = tid; i < NOCT * REP; i += BLOCK) {
                int q = i / REP, c = i - q * REP;
                float v1[8], v2[8];
#pragma unroll
                for (int k = 0; k < 8; ++k) {
                    int gr = rowbase + 8 * q + k;
                    v1[k] = (gr < N) ? x1[(size_t)gr * REP + c] : 0.f;
                    v2[k] = (gr < N) ? x2[(size_t)gr * REP + c] : 0.f;
                }
                ((float4*)xs)[i * 2]                    = make_float4(v1[0], v1[1], v1[2], v1[3]);
                ((float4*)xs)[i * 2 + 1]                = make_float4(v1[4], v1[5], v1[6], v1[7]);
                ((float4*)xs)[(NOCT * REP + i) * 2]     = make_float4(v2[0], v2[1], v2[2], v2[3]);
                ((float4*)xs)[(NOCT * REP + i) * 2 + 1] = make_float4(v2[4], v2[5], v2[6], v2[7]);
            }
        }
        __syncthreads();

        int oct = w & (NOCT - 1);
        int seg = w >> 1;
        int lo = g_q[seg], hi = g_q[seg + 1];
        // per-lane base: channel (oct*REP + lane), elements of 16 B, 2 per channel
        const ulonglong2* p1 = (const ulonglong2*)smraw + (oct * REP + lane) * 2;
        const ulonglong2* p2 = p1 + NOCT * REP * 2;
        const uint4* P = (const uint4*)g_prog;
        int gr0 = rowbase + 8 * oct;
        int full = (gr0 + 7 < N);
        float* ob = out + (size_t)gr0 * out_dim + lane;
        int od = out_dim;

        unsigned long long acc0 = 0ull, acc1 = 0ull, acc2 = 0ull, acc3 = 0ull;
#pragma unroll 4
        for (int s = lo; s < hi; ++s) {
            uint4 st = P[s];                                  // warp-uniform LDG.128
            unsigned ax = st.x;
            int ia = (int)(ax & 1023u) * 2;
            int ib = (int)((ax >> 10) & 1023u) * 2;
            ulonglong2 va0 = p1[ia], va1 = p1[ia + 1];
            ulonglong2 vb0 = p2[ib], vb1 = p2[ib + 1];
            unsigned long long cg2 = ((unsigned long long)st.w << 32) | st.z;
            unsigned long long m;
            asm("mul.rn.f32x2 %0, %1, %2;" : "=l"(m) : "l"(va0.x), "l"(vb0.x));
            asm("fma.rn.f32x2 %0, %1, %2, %3;" : "=l"(acc0) : "l"(m), "l"(cg2), "l"(acc0));
            asm("mul.rn.f32x2 %0, %1, %2;" : "=l"(m) : "l"(va0.y), "l"(vb0.y));
            asm("fma.rn.f32x2 %0, %1, %2, %3;" : "=l"(acc1) : "l"(m), "l"(cg2), "l"(acc1));
            asm("mul.rn.f32x2 %0, %1, %2;" : "=l"(m) : "l"(va1.x), "l"(vb1.x));
            asm("fma.rn.f32x2 %0, %1, %2, %3;" : "=l"(acc2) : "l"(m), "l"(cg2), "l"(acc2));
            asm("mul.rn.f32x2 %0, %1, %2;" : "=l"(m) : "l"(va1.y), "l"(vb1.y));
            asm("fma.rn.f32x2 %0, %1, %2, %3;" : "=l"(acc3) : "l"(m), "l"(cg2), "l"(acc3));
            if ((int)ax < 0) {                                // flush bit
                int o = (int)((ax >> 20) & 31u) << 5;
                if (o + lane < od) {
                    float* op = ob + o;
                    if (full) {
                        op[0]              = __uint_as_float((unsigned)acc0);
                        op[(size_t)od]     = __uint_as_float((unsigned)(acc0 >> 32));
                        op[2 * (size_t)od] = __uint_as_float((unsigned)acc1);
                        op[3 * (size_t)od] = __uint_as_float((unsigned)(acc1 >> 32));
                        op[4 * (size_t)od] = __uint_as_float((unsigned)acc2);
                        op[5 * (size_t)od] = __uint_as_float((unsigned)(acc2 >> 32));
                        op[6 * (size_t)od] = __uint_as_float((unsigned)acc3);
                        op[7 * (size_t)od] = __uint_as_float((unsigned)(acc3 >> 32));
                    } else {
                        unsigned r[8] = {(unsigned)acc0, (unsigned)(acc0 >> 32),
                                         (unsigned)acc1, (unsigned)(acc1 >> 32),
                                         (unsigned)acc2, (unsigned)(acc2 >> 32),
                                         (unsigned)acc3, (unsigned)(acc3 >> 32)};
#pragma unroll
                        for (int k = 0; k < 8; ++k)
                            if (gr0 + k < N) op[k * (size_t)od] = __uint_as_float(r[k]);
                    }
                }
                acc0 = acc1 = acc2 = acc3 = 0ull;
            }
        }
    } else {
        // -------- correct-but-slow fallback (never taken for this generator) ----
        float* f1 = (float*)smraw;                 // [16][640]
        float* f2 = f1 + ROWS * REP;
        for (int i = tid; i < ROWS * REP; i += BLOCK) {
            int r = i / REP, c = i - r * REP;
            int gr = rowbase + r;
            f1[i] = (gr < N) ? x1[(size_t)gr * REP + c] : 0.f;
            f2[i] = (gr < N) ? x2[(size_t)gr * REP + c] : 0.f;
        }
        for (int i = tid; i < ROWS * out_dim; i += BLOCK) {
            int gr = rowbase + i / out_dim;
            if (gr < N) out[(size_t)gr * out_dim + (i % out_dim)] = 0.f;
        }
        __syncthreads();
        int is64 = g_is64;
        for (int e = tid; e < M; e += BLOCK) {
            int a = geti(r1, e, is64), b = geti(r2, e, is64), o = geti(ro, e, is64);
            float c = cg[e];
            if ((unsigned)a >= (unsigned)REP || (unsigned)b >= (unsigned)REP ||
                (unsigned)o >= (unsigned)out_dim) continue;
            for (int r = 0; r < ROWS; ++r) {
                int gr = rowbase + r;
                if (gr < N)
                    atomicAdd(&out[(size_t)gr * out_dim + o],
                              c * f1[r * REP + a] * f2[r * REP + b]);
            }
        }
    }
}

// -------- launcher --------
extern "C" void kernel_launch(void* const* d_in, const int* in_sizes, int n_in,
                              void* d_out, int out_size) {
    const float* x1 = (const float*)d_in[0];
    const float* x2 = (const float*)d_in[1];
    const float* cg = (const float*)d_in[2];
    const void*  r1 = d_in[3];
    const void*  r2 = d_in[4];
    const void*  ro = d_in[5];

    int M = in_sizes[2];
    int N = in_sizes[0] / REP;
    int out_dim = out_size / N;

    k_prep<<<1, 1024>>>(r1, r2, ro, cg, M, out_dim);

    int smem = 2 * NOCT * REP * 32;                 // 81920 B
    cudaFuncSetAttribute(k_main, cudaFuncAttributeMaxDynamicSharedMemorySize, smem);
    k_main<<<(N + ROWS - 1) / ROWS, BLOCK, smem>>>(x1, x2, (float*)d_out,
                                                   N, out_dim, r1, r2, ro, cg, M);
}

// round 16
// speedup vs baseline: 1.7658x; 1.7658x over previous
#include <cuda_runtime.h>
#include <stdint.h>

#define REP      640
#define ROWS     16
#define NQUAD    4              // row quads per CTA
#define NSEG     8              // program octiles (4 quads x 8 segs = 32 warps)
#define NBIN     32             // 32-channel output bins (out_dim <= 1024)
#define MAXM     32768
#define MAXSTEP  1024
#define MAXPROG  (MAXSTEP + NBIN)
#define BLOCK    1024

// smem layout: [tiles 81920 | program 16896 | ctrl]
#define SMEM_PROG 81920
#define SMEM_CTRL (SMEM_PROG + MAXPROG * 16)

struct Ctrl {
    int sq[NSEG + 1];
    int irr;
    int is64;
    int S;
};

__device__ __forceinline__ int geti(const void* p, int i, int is64) {
    return is64 ? (int)((const long long*)p)[i] : ((const int*)p)[i];
}

// ---- single fused kernel: per-CTA prep (L2-hot) + R11 quad hot loop ----
__global__ __launch_bounds__(BLOCK, 2)
void k_main(const float* __restrict__ x1, const float* __restrict__ x2,
            float* __restrict__ out, int N, int out_dim,
            const void* __restrict__ r1, const void* __restrict__ r2,
            const void* __restrict__ ro, const float* __restrict__ cg, int M) {
    extern __shared__ __align__(16) char smraw[];
    float4* tiles = (float4*)smraw;                     // [2][NQUAD][REP]
    uint4*  sprog = (uint4*)(smraw + SMEM_PROG);        // {ab|bin<<20|fl<<31,0,cg,cg}
    Ctrl*   ctrl  = (Ctrl*)(smraw + SMEM_CTRL);

    // prep scratch aliases the tile region (tiles loaded after program build)
    unsigned*       sab  = (unsigned*)smraw;
    unsigned*       scgv = sab + MAXSTEP;
    unsigned short* sbin = (unsigned short*)(scgv + MAXSTEP);
    unsigned short* spos = sbin + MAXSTEP;
    int*            scnt = (int*)(spos + MAXSTEP);
    int*            sdum = scnt + NBIN;
    int*            sbas = sdum + NBIN;                 // NBIN + 1
    unsigned*       s_or = (unsigned*)(sbas + NBIN + 1);
    int*            s_ir = (int*)(s_or + 1);

    int tid  = threadIdx.x;
    int lane = tid & 31;
    int w    = tid >> 5;
    int rowbase = blockIdx.x * ROWS;
    const unsigned* cgu = (const unsigned*)cg;

    // ================= per-CTA prep =================
    if (tid < NBIN) { scnt[tid] = 0; sdum[tid] = 0; }
    if (tid == 0) { *s_or = 0u; *s_ir = ((M & 31) || M > MAXM) ? 1 : 0; }
    __syncthreads();
    int Mc = (M > MAXM) ? MAXM : M;

    // int64 detect: odd 32-bit words of ro all zero -> int64
    {
        const unsigned* rr = (const unsigned*)ro;
        int lim = (Mc < 4096) ? Mc : 4096;
        unsigned v = 0;
        for (int i = 1 + 2 * tid; i < lim; i += 2 * BLOCK) v |= rr[i];
        if (v) *s_or = 1u;                              // benign race
    }
    __syncthreads();
    int is64 = (*s_or == 0u);

    // verify + emit: i = base + tid, so i%32 == lane; lane0 = step head
    for (int base = 0; base < Mc; base += BLOCK) {
        int i = base + tid;
        int act = (i < Mc);
        int a = 0, b = 0, o = 0; unsigned cv = 0u;
        if (act) {
            a = geti(r1, i, is64); b = geti(r2, i, is64);
            o = geti(ro, i, is64); cv = cgu[i];
        }
        int pa = __shfl_up_sync(0xffffffffu, a, 1);
        int pb = __shfl_up_sync(0xffffffffu, b, 1);
        int po = __shfl_up_sync(0xffffffffu, o, 1);
        unsigned pc = __shfl_up_sync(0xffffffffu, cv, 1);
        if (act) {
            if (lane) {
                if (a != pa + 1 || b != pb + 1 || o != po + 1 || cv != pc)
                    *s_ir = 1;
            } else {
                int s = i >> 5;
                int bin = o >> 5;
                if ((o & 31) || (unsigned)a > (unsigned)(REP - 32) ||
                    (unsigned)b > (unsigned)(REP - 32) || (unsigned)bin >= NBIN) {
                    *s_ir = 1; a = 0; b = 0; bin = 0;
                }
                sab[s]  = (unsigned)a | ((unsigned)b << 10);
                scgv[s] = cv;
                sbin[s] = (unsigned short)bin;
                spos[s] = (unsigned short)atomicAdd(&scnt[bin], 1);
            }
        }
    }
    __syncthreads();

    // covered empty bins get one dummy slot (flush of acc=0 zero-fills block)
    int nblk = (out_dim + 31) >> 5;
    if (nblk > NBIN) nblk = NBIN;
    if (tid < nblk && scnt[tid] == 0) { scnt[tid] = 1; sdum[tid] = 1; }
    __syncthreads();

    // warp-0 shuffle scan over 32 bins
    if (tid < 32) {
        int v = scnt[tid], inc = v;
        for (int off = 1; off < 32; off <<= 1) {
            int u = __shfl_up_sync(0xffffffffu, inc, off);
            if (tid >= off) inc += u;
        }
        sbas[tid] = inc - v;
        if (tid == 31) sbas[32] = inc;
    }
    __syncthreads();

    if (tid == 0) {
        int Sp = sbas[NBIN];
        ctrl->irr = *s_ir;
        ctrl->is64 = is64;
        ctrl->S = Sp;
        ctrl->sq[0] = 0; ctrl->sq[NSEG] = Sp;
        for (int k = 1; k < NSEG; ++k) {
            int target = (Sp * k) / NSEG, best = 0, bd = 1 << 30;
            for (int b = 0; b <= NBIN; ++b) {
                int d = sbas[b] - target; if (d < 0) d = -d;
                if (d < bd) { bd = d; best = sbas[b]; }
            }
            ctrl->sq[k] = best;
        }
    }
    __syncthreads();

    // scatter into bin-ordered smem program; flush bit on last slot of each bin
    for (int s = tid; s < (Mc >> 5); s += BLOCK) {
        int bin = sbin[s];
        int slot = sbas[bin] + spos[s];
        unsigned fl = (slot == sbas[bin + 1] - 1) ? 0x80000000u : 0u;
        sprog[slot] = make_uint4(sab[s] | ((unsigned)bin << 20) | fl,
                                 0u, scgv[s], scgv[s]);
    }
    if (tid < NBIN && sdum[tid])
        sprog[sbas[tid]] = make_uint4(((unsigned)tid << 20) | 0x80000000u, 0u, 0u, 0u);
    __syncthreads();

    // ================= main phase =================
    if (!ctrl->irr) {
        float4* xs1 = tiles;                            // [NQUAD][REP]
        float4* xs2 = xs1 + NQUAD * REP;

        if (rowbase + ROWS <= N) {
            for (int i = tid; i < NQUAD * REP; i += BLOCK) {
                int q = i / REP, c = i - q * REP;
                const float* b1 = x1 + (size_t)(rowbase + 4 * q) * REP + c;
                const float* b2 = x2 + (size_t)(rowbase + 4 * q) * REP + c;
                xs1[i] = make_float4(b1[0], b1[REP], b1[2 * REP], b1[3 * REP]);
                xs2[i] = make_float4(b2[0], b2[REP], b2[2 * REP], b2[3 * REP]);
            }
        } else {
            for (int i = tid; i < NQUAD * REP; i += BLOCK) {
                int q = i / REP, c = i - q * REP;
                float v1[4], v2[4];
#pragma unroll
                for (int k = 0; k < 4; ++k) {
                    int gr = rowbase + 4 * q + k;
                    v1[k] = (gr < N) ? x1[(size_t)gr * REP + c] : 0.f;
                    v2[k] = (gr < N) ? x2[(size_t)gr * REP + c] : 0.f;
                }
                xs1[i] = make_float4(v1[0], v1[1], v1[2], v1[3]);
                xs2[i] = make_float4(v2[0], v2[1], v2[2], v2[3]);
            }
        }
        __syncthreads();

        int quad = w & (NQUAD - 1);
        int seg  = w >> 2;
        int lo = ctrl->sq[seg], hi = ctrl->sq[seg + 1];
        const ulonglong2* p1 = (const ulonglong2*)xs1 + quad * REP + lane;
        const ulonglong2* p2 = p1 + NQUAD * REP;
        int gr0 = rowbase + 4 * quad;
        int full = (gr0 + 3 < N);
        float* ob = out + (size_t)gr0 * out_dim + lane;
        int od = out_dim;

        unsigned long long acc0 = 0ull, acc1 = 0ull;
#pragma unroll 4
        for (int s = lo; s < hi; ++s) {
            uint4 st = sprog[s];                        // warp-uniform LDS.128
            unsigned ax = st.x;
            ulonglong2 va = p1[ax & 1023u];
            ulonglong2 vb = p2[(ax >> 10) & 1023u];
            unsigned long long cg2 = ((unsigned long long)st.w << 32) | st.z;
            unsigned long long m0, m1;
            asm("mul.rn.f32x2 %0, %1, %2;" : "=l"(m0) : "l"(va.x), "l"(vb.x));
            asm("fma.rn.f32x2 %0, %1, %2, %3;" : "=l"(acc0) : "l"(m0), "l"(cg2), "l"(acc0));
            asm("mul.rn.f32x2 %0, %1, %2;" : "=l"(m1) : "l"(va.y), "l"(vb.y));
            asm("fma.rn.f32x2 %0, %1, %2, %3;" : "=l"(acc1) : "l"(m1), "l"(cg2), "l"(acc1));
            if ((int)ax < 0) {                          // flush bit
                int o = (int)((ax >> 20) & 31u) << 5;
                if (o + lane < od) {
                    float* op = ob + o;
                    if (full) {
                        op[0]              = __uint_as_float((unsigned)acc0);
                        op[(size_t)od]     = __uint_as_float((unsigned)(acc0 >> 32));
                        op[2 * (size_t)od] = __uint_as_float((unsigned)acc1);
                        op[3 * (size_t)od] = __uint_as_float((unsigned)(acc1 >> 32));
                    } else {
                        if (gr0 + 0 < N) op[0]              = __uint_as_float((unsigned)acc0);
                        if (gr0 + 1 < N) op[(size_t)od]     = __uint_as_float((unsigned)(acc0 >> 32));
                        if (gr0 + 2 < N) op[2 * (size_t)od] = __uint_as_float((unsigned)acc1);
                        if (gr0 + 3 < N) op[3 * (size_t)od] = __uint_as_float((unsigned)(acc1 >> 32));
                    }
                }
                acc0 = 0ull; acc1 = 0ull;
            }
        }
    } else {
        // -------- correct-but-slow fallback (never taken for this generator) ----
        int is64f = ctrl->is64;
        float* f1 = (float*)smraw;                      // [16][640]
        float* f2 = f1 + ROWS * REP;
        for (int i = tid; i < ROWS * REP; i += BLOCK) {
            int r = i / REP, c = i - r * REP;
            int gr = rowbase + r;
            f1[i] = (gr < N) ? x1[(size_t)gr * REP + c] : 0.f;
            f2[i] = (gr < N) ? x2[(size_t)gr * REP + c] : 0.f;
        }
        for (int i = tid; i < ROWS * out_dim; i += BLOCK) {
            int gr = rowbase + i / out_dim;
            if (gr < N) out[(size_t)gr * out_dim + (i % out_dim)] = 0.f;
        }
        __syncthreads();
        for (int e = tid; e < M; e += BLOCK) {
            int a = geti(r1, e, is64f), b = geti(r2, e, is64f), o = geti(ro, e, is64f);
            float c = cg[e];
            if ((unsigned)a >= (unsigned)REP || (unsigned)b >= (unsigned)REP ||
                (unsigned)o >= (unsigned)out_dim) continue;
            for (int r = 0; r < ROWS; ++r) {
                int gr = rowbase + r;
                if (gr < N)
                    atomicAdd(&out[(size_t)gr * out_dim + o],
                              c * f1[r * REP + a] * f2[r * REP + b]);
            }
        }
    }
}

// -------- launcher: ONE kernel --------
extern "C" void kernel_launch(void* const* d_in, const int* in_sizes, int n_in,
                              void* d_out, int out_size) {
    const float* x1 = (const float*)d_in[0];
    const float* x2 = (const float*)d_in[1];
    const float* cg = (const float*)d_in[2];
    const void*  r1 = d_in[3];
    const void*  r2 = d_in[4];
    const void*  ro = d_in[5];

    int M = in_sizes[2];
    int N = in_sizes[0] / REP;
    int out_dim = out_size / N;

    int smem = SMEM_CTRL + (int)sizeof(Ctrl);          // 98864 + 48
    cudaFuncSetAttribute(k_main, cudaFuncAttributeMaxDynamicSharedMemorySize, smem);
    k_main<<<(N + ROWS - 1) / ROWS, BLOCK, smem>>>(x1, x2, (float*)d_out,
                                                   N, out_dim, r1, r2, ro, cg, M);
}